// round 5
// baseline (speedup 1.0000x reference)
#include <cuda_runtime.h>

#define B_  1024
#define S_  1024
#define E_  12
#define NQ  12
#define EPS_ 1e-5f

#define SPB 40    // s-values per block (4 warps x 10 groups)
#define BCH 16    // batches per block (b-loop)

// Per-sequence-position broadcast vectors (indexed by s, 0..1023)
__device__ float g_attn[S_ * E_];
__device__ float g_ffn [S_ * E_];   // holds ffn[s] + b1 (b1 folded in prep)

__constant__ float c_g1[12];
__constant__ float c_g2[12];
__constant__ float c_b2[12];

// ---------------------------------------------------------------------------
// Prep: one block per s (0..1023). Computes g_attn[s,:], g_ffn[s,:] (+b1).
// ---------------------------------------------------------------------------
__global__ void __launch_bounds__(32) prep_kernel(
    const float* __restrict__ x,
    const float* __restrict__ rx,
    const float* __restrict__ ry,
    const float* __restrict__ w_ffn,
    const float* __restrict__ b_ffn,
    const float* __restrict__ g1,
    const float* __restrict__ b1)
{
    const int s = blockIdx.x;
    const int t = threadIdx.x;

    __shared__ float xt[NQ * E_];        // x[s, 0:12, 0:12]
    __shared__ float corner[NQ * NQ];    // corner[j*12+i] = x[j, i, 0]
    __shared__ float crx[NQ];
    __shared__ float attn_c[NQ * NQ];    // attn rows for s'=0..11
    __shared__ float attn_own[NQ];
    __shared__ float z[NQ];

    const float* xs = x + (size_t)s * (S_ * E_);
    for (int k = t; k < NQ * E_; k += 32) xt[k] = xs[k];
    for (int k = t; k < NQ * NQ; k += 32) {
        const int j = k / NQ, i = k % NQ;
        corner[k] = x[(size_t)j * (S_ * E_) + i * E_];
    }
    if (t < NQ) crx[t] = cosf(rx[t]);
    __syncwarp();

    if (t < NQ) {
        float d[NQ];
        #pragma unroll
        for (int i = 0; i < NQ; i++) d[i] = crx[i] * cosf(corner[t * NQ + i]);
        float p = 1.f;
        #pragma unroll
        for (int i = 0; i < NQ; i++) { p *= d[i]; if (i >= 1) attn_c[t * NQ + i] = p; }
        float q = 1.f;
        #pragma unroll
        for (int i = 1; i < NQ; i++) q *= d[i];
        attn_c[t * NQ + 0] = q;
    } else if (t == 12) {
        float d[NQ];
        #pragma unroll
        for (int i = 0; i < NQ; i++) d[i] = crx[i] * cosf(xt[i * E_]);
        float p = 1.f;
        #pragma unroll
        for (int i = 0; i < NQ; i++) { p *= d[i]; if (i >= 1) attn_own[i] = p; }
        float q = 1.f;
        #pragma unroll
        for (int i = 1; i < NQ; i++) q *= d[i];
        attn_own[0] = q;
    }
    __syncwarp();

    if (t < NQ) {
        float v[E_];
        float mu = 0.f;
        #pragma unroll
        for (int e = 0; e < E_; e++) { v[e] = xt[t * E_ + e] + attn_c[t * NQ + e]; mu += v[e]; }
        mu *= (1.f / E_);
        float var = 0.f;
        #pragma unroll
        for (int e = 0; e < E_; e++) { float dd = v[e] - mu; var += dd * dd; }
        var *= (1.f / E_);
        const float tok2 = (v[0] - mu) * rsqrtf(var + EPS_) * g1[0] + b1[0];
        z[t] = fmaxf(cosf(ry[t] + tok2), 0.f);
    }
    __syncwarp();

    if (t < E_) {
        float f = b_ffn[t] + b1[t];                 // fold b1 into ffn
        #pragma unroll
        for (int j = 0; j < NQ; j++) f += z[j] * w_ffn[t * NQ + j];
        g_ffn [s * E_ + t] = f;
        g_attn[s * E_ + t] = attn_own[t];
    }
}

// ---------------------------------------------------------------------------
// Main: out[b,s,:] = LN2( LN1(x[b,s,:] + attn[s,:])*g1 + (ffn[s,:]+b1) )
// 3 lanes per s (one float4 chunk each). Each group loops over BCH batches;
// attn/ffn chunks are loop-invariant registers. Params in __constant__.
// x/out accesses fully coalesced float4; LN stats via 8 shuffles per row.
// ---------------------------------------------------------------------------
#define ACTIVE_MASK 0x3FFFFFFFu

__global__ void __launch_bounds__(128) main_kernel(
    const float* __restrict__ x,
    float* __restrict__ out)
{
    const int lane = threadIdx.x & 31;
    if (lane >= 30) return;

    const int warp = threadIdx.x >> 5;
    const int g = lane / 3;
    const int c = lane - g * 3;
    const int base = g * 3;
    // cyclic reduction partner lanes (exclude self)
    const int i1 = (c == 2) ? base     : lane + 1;
    const int i2 = (c == 0) ? base + 2 : lane - 1;

    const int sg = blockIdx.x * SPB + warp * 10 + g;
    const bool valid = (sg < S_);
    const int s = valid ? sg : S_ - 1;
    const int b0 = blockIdx.y * BCH;

    const float4 va = ((const float4*)g_attn)[s * 3 + c];
    const float4 vf = ((const float4*)g_ffn )[s * 3 + c];
    const float g1x = c_g1[c*4+0], g1y = c_g1[c*4+1], g1z = c_g1[c*4+2], g1w = c_g1[c*4+3];
    const float g2x = c_g2[c*4+0], g2y = c_g2[c*4+1], g2z = c_g2[c*4+2], g2w = c_g2[c*4+3];
    const float b2x = c_b2[c*4+0], b2y = c_b2[c*4+1], b2z = c_b2[c*4+2], b2w = c_b2[c*4+3];

    const size_t stride = (size_t)S_ * 3;                    // float4 stride per batch
    const float4* __restrict__ px = (const float4*)x   + ((size_t)b0 * S_ + s) * 3 + c;
    float4*       __restrict__ po = (float4*)out       + ((size_t)b0 * S_ + s) * 3 + c;

    #pragma unroll 4
    for (int i = 0; i < BCH; i++) {
        const float4 vx = px[(size_t)i * stride];
        float v0 = vx.x + va.x, v1 = vx.y + va.y, v2 = vx.z + va.z, v3 = vx.w + va.w;

        // LN1 stats (3-lane cyclic reduction, 4 shuffles)
        float ps = (v0 + v1) + (v2 + v3);
        float pq = fmaf(v0, v0, v1 * v1) + fmaf(v2, v2, v3 * v3);
        float sum = ps + __shfl_sync(ACTIVE_MASK, ps, i1) + __shfl_sync(ACTIVE_MASK, ps, i2);
        float sq  = pq + __shfl_sync(ACTIVE_MASK, pq, i1) + __shfl_sync(ACTIVE_MASK, pq, i2);
        float mu  = sum * (1.f / 12.f);
        float var = fmaxf(sq * (1.f / 12.f) - mu * mu, 0.f);
        float inv = rsqrtf(var + EPS_);

        v0 = (v0 - mu) * inv * g1x + vf.x;
        v1 = (v1 - mu) * inv * g1y + vf.y;
        v2 = (v2 - mu) * inv * g1z + vf.z;
        v3 = (v3 - mu) * inv * g1w + vf.w;

        // LN2 stats
        ps = (v0 + v1) + (v2 + v3);
        pq = fmaf(v0, v0, v1 * v1) + fmaf(v2, v2, v3 * v3);
        sum = ps + __shfl_sync(ACTIVE_MASK, ps, i1) + __shfl_sync(ACTIVE_MASK, ps, i2);
        sq  = pq + __shfl_sync(ACTIVE_MASK, pq, i1) + __shfl_sync(ACTIVE_MASK, pq, i2);
        mu  = sum * (1.f / 12.f);
        var = fmaxf(sq * (1.f / 12.f) - mu * mu, 0.f);
        inv = rsqrtf(var + EPS_);

        if (valid) {
            float4 o;
            o.x = (v0 - mu) * inv * g2x + b2x;
            o.y = (v1 - mu) * inv * g2y + b2y;
            o.z = (v2 - mu) * inv * g2z + b2z;
            o.w = (v3 - mu) * inv * g2w + b2w;
            po[(size_t)i * stride] = o;
        }
    }
}

extern "C" void kernel_launch(void* const* d_in, const int* in_sizes, int n_in,
                              void* d_out, int out_size)
{
    const float* x     = (const float*)d_in[0];
    const float* rx    = (const float*)d_in[1];
    const float* ry    = (const float*)d_in[2];
    const float* w_ffn = (const float*)d_in[3];
    const float* b_ffn = (const float*)d_in[4];
    const float* g1    = (const float*)d_in[5];
    const float* b1    = (const float*)d_in[6];
    const float* g2    = (const float*)d_in[7];
    const float* b2    = (const float*)d_in[8];
    float* out = (float*)d_out;

    cudaMemcpyToSymbolAsync(c_g1, g1, 12 * sizeof(float), 0, cudaMemcpyDeviceToDevice);
    cudaMemcpyToSymbolAsync(c_g2, g2, 12 * sizeof(float), 0, cudaMemcpyDeviceToDevice);
    cudaMemcpyToSymbolAsync(c_b2, b2, 12 * sizeof(float), 0, cudaMemcpyDeviceToDevice);

    prep_kernel<<<S_, 32>>>(x, rx, ry, w_ffn, b_ffn, g1, b1);

    dim3 grid((S_ + SPB - 1) / SPB, B_ / BCH);   // 26 x 64
    main_kernel<<<grid, 128>>>(x, out);
}

// round 6
// speedup vs baseline: 1.0091x; 1.0091x over previous
#include <cuda_runtime.h>

#define B_  1024
#define S_  1024
#define E_  12
#define NQ  12
#define EPS_ 1e-5f

#define SPB 40    // s-values per block (4 warps x 10 groups)
#define BCH 16    // batches per block (b-loop)

// Per-sequence-position broadcast vectors (indexed by s, 0..1023)
__device__ float g_attn[S_ * E_];
__device__ float g_ffn [S_ * E_];   // holds ffn[s] + b1 (b1 folded in prep)

__constant__ float c_g1[12];
__constant__ float c_g2[12];
__constant__ float c_b2[12];

// ---------------------------------------------------------------------------
// Prep: one block per s (0..1023). Computes g_attn[s,:], g_ffn[s,:] (+b1).
// ---------------------------------------------------------------------------
__global__ void __launch_bounds__(32) prep_kernel(
    const float* __restrict__ x,
    const float* __restrict__ rx,
    const float* __restrict__ ry,
    const float* __restrict__ w_ffn,
    const float* __restrict__ b_ffn,
    const float* __restrict__ g1,
    const float* __restrict__ b1)
{
    const int s = blockIdx.x;
    const int t = threadIdx.x;

    __shared__ float xt[NQ * E_];        // x[s, 0:12, 0:12]
    __shared__ float corner[NQ * NQ];    // corner[j*12+i] = x[j, i, 0]
    __shared__ float crx[NQ];
    __shared__ float attn_c[NQ * NQ];    // attn rows for s'=0..11
    __shared__ float attn_own[NQ];
    __shared__ float z[NQ];

    const float* xs = x + (size_t)s * (S_ * E_);
    for (int k = t; k < NQ * E_; k += 32) xt[k] = xs[k];
    for (int k = t; k < NQ * NQ; k += 32) {
        const int j = k / NQ, i = k % NQ;
        corner[k] = x[(size_t)j * (S_ * E_) + i * E_];
    }
    if (t < NQ) crx[t] = cosf(rx[t]);
    __syncwarp();

    if (t < NQ) {
        float d[NQ];
        #pragma unroll
        for (int i = 0; i < NQ; i++) d[i] = crx[i] * cosf(corner[t * NQ + i]);
        float p = 1.f;
        #pragma unroll
        for (int i = 0; i < NQ; i++) { p *= d[i]; if (i >= 1) attn_c[t * NQ + i] = p; }
        float q = 1.f;
        #pragma unroll
        for (int i = 1; i < NQ; i++) q *= d[i];
        attn_c[t * NQ + 0] = q;
    } else if (t == 12) {
        float d[NQ];
        #pragma unroll
        for (int i = 0; i < NQ; i++) d[i] = crx[i] * cosf(xt[i * E_]);
        float p = 1.f;
        #pragma unroll
        for (int i = 0; i < NQ; i++) { p *= d[i]; if (i >= 1) attn_own[i] = p; }
        float q = 1.f;
        #pragma unroll
        for (int i = 1; i < NQ; i++) q *= d[i];
        attn_own[0] = q;
    }
    __syncwarp();

    if (t < NQ) {
        float v[E_];
        float mu = 0.f;
        #pragma unroll
        for (int e = 0; e < E_; e++) { v[e] = xt[t * E_ + e] + attn_c[t * NQ + e]; mu += v[e]; }
        mu *= (1.f / E_);
        float var = 0.f;
        #pragma unroll
        for (int e = 0; e < E_; e++) { float dd = v[e] - mu; var += dd * dd; }
        var *= (1.f / E_);
        const float tok2 = (v[0] - mu) * rsqrtf(var + EPS_) * g1[0] + b1[0];
        z[t] = fmaxf(cosf(ry[t] + tok2), 0.f);
    }
    __syncwarp();

    if (t < E_) {
        float f = b_ffn[t] + b1[t];                 // fold b1 into ffn
        #pragma unroll
        for (int j = 0; j < NQ; j++) f += z[j] * w_ffn[t * NQ + j];
        g_ffn [s * E_ + t] = f;
        g_attn[s * E_ + t] = attn_own[t];
    }
}

// ---------------------------------------------------------------------------
// Main: out[b,s,:] = LN2( LN1(x[b,s,:] + attn[s,:])*g1 + (ffn[s,:]+b1) )
// 3 lanes per s (one float4 chunk each). Each group loops over BCH batches;
// attn/ffn chunks are loop-invariant registers. Params in __constant__.
// x/out accesses fully coalesced float4; LN stats via 8 shuffles per row.
// ---------------------------------------------------------------------------
#define ACTIVE_MASK 0x3FFFFFFFu

__global__ void __launch_bounds__(128) main_kernel(
    const float* __restrict__ x,
    float* __restrict__ out)
{
    const int lane = threadIdx.x & 31;
    if (lane >= 30) return;

    const int warp = threadIdx.x >> 5;
    const int g = lane / 3;
    const int c = lane - g * 3;
    const int base = g * 3;
    // cyclic reduction partner lanes (exclude self)
    const int i1 = (c == 2) ? base     : lane + 1;
    const int i2 = (c == 0) ? base + 2 : lane - 1;

    const int sg = blockIdx.x * SPB + warp * 10 + g;
    const bool valid = (sg < S_);
    const int s = valid ? sg : S_ - 1;
    const int b0 = blockIdx.y * BCH;

    const float4 va = ((const float4*)g_attn)[s * 3 + c];
    const float4 vf = ((const float4*)g_ffn )[s * 3 + c];
    const float g1x = c_g1[c*4+0], g1y = c_g1[c*4+1], g1z = c_g1[c*4+2], g1w = c_g1[c*4+3];
    const float g2x = c_g2[c*4+0], g2y = c_g2[c*4+1], g2z = c_g2[c*4+2], g2w = c_g2[c*4+3];
    const float b2x = c_b2[c*4+0], b2y = c_b2[c*4+1], b2z = c_b2[c*4+2], b2w = c_b2[c*4+3];

    const size_t stride = (size_t)S_ * 3;                    // float4 stride per batch
    const float4* __restrict__ px = (const float4*)x   + ((size_t)b0 * S_ + s) * 3 + c;
    float4*       __restrict__ po = (float4*)out       + ((size_t)b0 * S_ + s) * 3 + c;

    #pragma unroll 4
    for (int i = 0; i < BCH; i++) {
        const float4 vx = px[(size_t)i * stride];
        float v0 = vx.x + va.x, v1 = vx.y + va.y, v2 = vx.z + va.z, v3 = vx.w + va.w;

        // LN1 stats (3-lane cyclic reduction, 4 shuffles)
        float ps = (v0 + v1) + (v2 + v3);
        float pq = fmaf(v0, v0, v1 * v1) + fmaf(v2, v2, v3 * v3);
        float sum = ps + __shfl_sync(ACTIVE_MASK, ps, i1) + __shfl_sync(ACTIVE_MASK, ps, i2);
        float sq  = pq + __shfl_sync(ACTIVE_MASK, pq, i1) + __shfl_sync(ACTIVE_MASK, pq, i2);
        float mu  = sum * (1.f / 12.f);
        float var = fmaxf(sq * (1.f / 12.f) - mu * mu, 0.f);
        float inv = rsqrtf(var + EPS_);

        v0 = (v0 - mu) * inv * g1x + vf.x;
        v1 = (v1 - mu) * inv * g1y + vf.y;
        v2 = (v2 - mu) * inv * g1z + vf.z;
        v3 = (v3 - mu) * inv * g1w + vf.w;

        // LN2 stats
        ps = (v0 + v1) + (v2 + v3);
        pq = fmaf(v0, v0, v1 * v1) + fmaf(v2, v2, v3 * v3);
        sum = ps + __shfl_sync(ACTIVE_MASK, ps, i1) + __shfl_sync(ACTIVE_MASK, ps, i2);
        sq  = pq + __shfl_sync(ACTIVE_MASK, pq, i1) + __shfl_sync(ACTIVE_MASK, pq, i2);
        mu  = sum * (1.f / 12.f);
        var = fmaxf(sq * (1.f / 12.f) - mu * mu, 0.f);
        inv = rsqrtf(var + EPS_);

        if (valid) {
            float4 o;
            o.x = (v0 - mu) * inv * g2x + b2x;
            o.y = (v1 - mu) * inv * g2y + b2y;
            o.z = (v2 - mu) * inv * g2z + b2z;
            o.w = (v3 - mu) * inv * g2w + b2w;
            po[(size_t)i * stride] = o;
        }
    }
}

extern "C" void kernel_launch(void* const* d_in, const int* in_sizes, int n_in,
                              void* d_out, int out_size)
{
    const float* x     = (const float*)d_in[0];
    const float* rx    = (const float*)d_in[1];
    const float* ry    = (const float*)d_in[2];
    const float* w_ffn = (const float*)d_in[3];
    const float* b_ffn = (const float*)d_in[4];
    const float* g1    = (const float*)d_in[5];
    const float* b1    = (const float*)d_in[6];
    const float* g2    = (const float*)d_in[7];
    const float* b2    = (const float*)d_in[8];
    float* out = (float*)d_out;

    cudaMemcpyToSymbolAsync(c_g1, g1, 12 * sizeof(float), 0, cudaMemcpyDeviceToDevice);
    cudaMemcpyToSymbolAsync(c_g2, g2, 12 * sizeof(float), 0, cudaMemcpyDeviceToDevice);
    cudaMemcpyToSymbolAsync(c_b2, b2, 12 * sizeof(float), 0, cudaMemcpyDeviceToDevice);

    prep_kernel<<<S_, 32>>>(x, rx, ry, w_ffn, b_ffn, g1, b1);

    dim3 grid((S_ + SPB - 1) / SPB, B_ / BCH);   // 26 x 64
    main_kernel<<<grid, 128>>>(x, out);
}